// round 15
// baseline (speedup 1.0000x reference)
#include <cuda_runtime.h>
#include <cuda_fp16.h>
#include <cstdint>

#define N_NODES 20000
#define IN_DIM 256
#define HID 128
#define OUT_DIM 64
#define N_LAYERS 4
#define N_PATHS 8
#define PATH_LEN 8
#define N_TYPES 2

// -------- scratch (no allocations allowed; device globals) --------
__device__ __align__(16) __half g_in_feats[N_NODES * HID];
__device__ __align__(16) __half g_bufA[N_NODES * HID];
__device__ __align__(16) __half g_bufB[N_NODES * HID];
__device__ __align__(16) __half g_fout[N_NODES * N_TYPES * HID];
__device__ __align__(16) __half g_x_h[N_NODES * IN_DIM];
__device__ __align__(16) __half g_wres_h[N_LAYERS * N_TYPES * PATH_LEN * HID];

#define W_IN_ELEMS    (HID * IN_DIM)
#define W_LAYER_ELEMS (N_LAYERS * HID * N_TYPES * HID)
#define W_OUT_ELEMS   (OUT_DIM * HID)
__device__ __align__(16) __half g_w_in[W_IN_ELEMS];
__device__ __align__(16) __half g_w_layer[W_LAYER_ELEMS];
__device__ __align__(16) __half g_w_out[W_OUT_ELEMS];

__device__ __forceinline__ void mma_f16(
    float& d0, float& d1, float& d2, float& d3,
    uint32_t a0, uint32_t a1, uint32_t a2, uint32_t a3,
    uint32_t b0, uint32_t b1)
{
    asm volatile(
        "mma.sync.aligned.m16n8k16.row.col.f32.f16.f16.f32 "
        "{%0,%1,%2,%3}, {%4,%5,%6,%7}, {%8,%9}, {%0,%1,%2,%3};\n"
        : "+f"(d0), "+f"(d1), "+f"(d2), "+f"(d3)
        : "r"(a0), "r"(a1), "r"(a2), "r"(a3), "r"(b0), "r"(b1));
}

__device__ __forceinline__ void cp_async16(void* smem_dst, const void* gsrc,
                                           int src_bytes) {
    uint32_t s = (uint32_t)__cvta_generic_to_shared(smem_dst);
    asm volatile("cp.async.cg.shared.global [%0], [%1], 16, %2;\n"
                 :: "r"(s), "l"(gsrc), "r"(src_bytes));
}
__device__ __forceinline__ void cp_async_commit() {
    asm volatile("cp.async.commit_group;\n");
}
template <int N>
__device__ __forceinline__ void cp_async_wait() {
    asm volatile("cp.async.wait_group %0;\n" :: "n"(N));
}

// ============================================================================
// Fused prep: fp16 conversions of x / weights, and wres = pw/count as fp16.
// ============================================================================
__global__ void prep_kernel(const float* __restrict__ x,
                            const float* __restrict__ w_in,
                            const float* __restrict__ w_layer,
                            const float* __restrict__ w_out,
                            const float* __restrict__ pw,
                            const int* __restrict__ ptypes)
{
    int i = blockIdx.x * blockDim.x + threadIdx.x;
    if (i < N_NODES * IN_DIM) g_x_h[i] = __float2half(__ldg(x + i));
    if (i < W_IN_ELEMS)       g_w_in[i] = __float2half(__ldg(w_in + i));
    if (i < W_LAYER_ELEMS)    g_w_layer[i] = __float2half(__ldg(w_layer + i));
    if (i < W_OUT_ELEMS)      g_w_out[i] = __float2half(__ldg(w_out + i));
    if (i < N_LAYERS * N_TYPES * PATH_LEN * HID) {
        int t = (i / (PATH_LEN * HID)) % N_TYPES;
        int cnt = 0;
#pragma unroll
        for (int p = 0; p < N_PATHS; p++) cnt += (__ldg(ptypes + p) == t);
        float inv = cnt > 0 ? 1.0f / (float)cnt : 0.0f;
        g_wres_h[i] = __float2half(__ldg(pw + i) * inv);
    }
}

// ============================================================================
// FP16 tensor-core GEMM (m16n8k16, fp32 accum), 4-stage cp.async pipeline.
//   C[M, BN] = EPI( A[M, KDIM] @ W[BN, KDIM]^T )
//   EPI==0: relu(acc + bias[n]);  EPI==1: 0.8*relu(acc)+0.1*pre+0.1*inf
//   OUTH: store C (and read pre/inf) as __half; else fp32.
// Block tile 64 x BN, 256 threads: 2 warps M x 4 warps N.
// ============================================================================
template <int KDIM, int BN, int EPI, bool OUTH>
__global__ void __launch_bounds__(256, 3)
gemm_h_kernel(const __half* __restrict__ A, const __half* __restrict__ W,
              const float* __restrict__ bias, const void* __restrict__ pre,
              const void* __restrict__ inf, void* __restrict__ C)
{
    constexpr int BM = 64, BK = 32, LDSH = 40, NST = 4;
    constexpr int NTW = BN / 32;
    constexpr int ASZ = BM * LDSH;
    constexpr int BSZ = BN * LDSH;
    constexpr int KTILES = KDIM / BK;
    constexpr int NCA = (BM * BK) / 8 / 256;
    constexpr int NCB = (BN * BK) / 8 / 256;

    extern __shared__ __half smh[];
    __half* As = smh;
    __half* Bs = smh + NST * ASZ;

    const int tid    = threadIdx.x;
    const int lane   = tid & 31;
    const int warp   = tid >> 5;
    const int warp_m = warp & 1;
    const int warp_n = warp >> 1;
    const int gid    = lane >> 2;
    const int tig    = lane & 3;
    const int m0     = blockIdx.x * BM;

    float acc[2][NTW][4];
#pragma unroll
    for (int mt = 0; mt < 2; mt++)
#pragma unroll
        for (int nt = 0; nt < NTW; nt++)
#pragma unroll
            for (int r = 0; r < 4; r++) acc[mt][nt][r] = 0.f;

    auto issue = [&](int kt, int b) {
#pragma unroll
        for (int i = 0; i < NCA; i++) {
            int c    = tid + i * 256;
            int row  = c >> 2, colh = (c & 3) << 3;
            int ok   = (m0 + row) < N_NODES ? 16 : 0;
            cp_async16(As + b * ASZ + row * LDSH + colh,
                       A + (size_t)(m0 + row) * KDIM + kt * BK + colh, ok);
        }
#pragma unroll
        for (int i = 0; i < NCB; i++) {
            int c    = tid + i * 256;
            int row  = c >> 2, colh = (c & 3) << 3;
            cp_async16(Bs + b * BSZ + row * LDSH + colh,
                       W + (size_t)row * KDIM + kt * BK + colh, 16);
        }
    };

#pragma unroll
    for (int s = 0; s < NST - 1; s++) {
        if (s < KTILES) issue(s, s);
        cp_async_commit();
    }

    for (int kt = 0; kt < KTILES; kt++) {
        if (kt + NST - 1 < KTILES) issue(kt + NST - 1, (kt + NST - 1) % NST);
        cp_async_commit();
        cp_async_wait<NST - 1>();
        __syncthreads();

        const __half* Ab = As + (kt % NST) * ASZ;
        const __half* Bb = Bs + (kt % NST) * BSZ;
#pragma unroll
        for (int kk = 0; kk < BK / 16; kk++) {
            const int kb = kk * 16;
            uint32_t a[2][4];
#pragma unroll
            for (int mt = 0; mt < 2; mt++) {
                int r = warp_m * 32 + mt * 16 + gid;
                a[mt][0] = *(const uint32_t*)(Ab + r * LDSH + kb + 2 * tig);
                a[mt][1] = *(const uint32_t*)(Ab + (r + 8) * LDSH + kb + 2 * tig);
                a[mt][2] = *(const uint32_t*)(Ab + r * LDSH + kb + 8 + 2 * tig);
                a[mt][3] = *(const uint32_t*)(Ab + (r + 8) * LDSH + kb + 8 + 2 * tig);
            }
            uint32_t b[NTW][2];
#pragma unroll
            for (int nt = 0; nt < NTW; nt++) {
                int c = warp_n * (NTW * 8) + nt * 8 + gid;
                b[nt][0] = *(const uint32_t*)(Bb + c * LDSH + kb + 2 * tig);
                b[nt][1] = *(const uint32_t*)(Bb + c * LDSH + kb + 8 + 2 * tig);
            }
#pragma unroll
            for (int mt = 0; mt < 2; mt++)
#pragma unroll
                for (int nt = 0; nt < NTW; nt++)
                    mma_f16(acc[mt][nt][0], acc[mt][nt][1],
                            acc[mt][nt][2], acc[mt][nt][3],
                            a[mt][0], a[mt][1], a[mt][2], a[mt][3],
                            b[nt][0], b[nt][1]);
        }
        __syncthreads();
    }

#pragma unroll
    for (int mt = 0; mt < 2; mt++) {
#pragma unroll
        for (int half = 0; half < 2; half++) {
            int row = m0 + warp_m * 32 + mt * 16 + half * 8 + gid;
            if (row >= N_NODES) continue;
#pragma unroll
            for (int nt = 0; nt < NTW; nt++) {
                int col = warp_n * (NTW * 8) + nt * 8 + 2 * tig;
                float v0 = acc[mt][nt][half * 2 + 0];
                float v1 = acc[mt][nt][half * 2 + 1];
                size_t off = (size_t)row * BN + col;
                if constexpr (EPI == 0) {
                    v0 = fmaxf(v0 + bias[col], 0.f);
                    v1 = fmaxf(v1 + bias[col + 1], 0.f);
                } else {
                    float2 p2, f2;
                    if constexpr (OUTH) {
                        p2 = __half22float2(*(const __half2*)((const __half*)pre + off));
                        f2 = __half22float2(*(const __half2*)((const __half*)inf + off));
                    } else {
                        p2 = *(const float2*)((const float*)pre + off);
                        f2 = *(const float2*)((const float*)inf + off);
                    }
                    v0 = 0.8f * fmaxf(v0, 0.f) + 0.1f * p2.x + 0.1f * f2.x;
                    v1 = 0.8f * fmaxf(v1, 0.f) + 0.1f * p2.y + 0.1f * f2.y;
                }
                if constexpr (OUTH) {
                    *(__half2*)((__half*)C + off) = __floats2half2_rn(v0, v1);
                } else {
                    *(float2*)((float*)C + off) = make_float2(v0, v1);
                }
            }
        }
    }
}

// ============================================================================
// Gather (unchanged from R14): 1 warp per node, lane covers 4 channels,
// l-outer, type-permuted indices, half2 pairwise-tree path sum, fp16 weights.
// 8 nodes per 256-thread block.
// ============================================================================
__device__ __forceinline__ __half* buf_ptr(int s) {
    return s == 0 ? g_in_feats : (s == 1 ? g_bufA : g_bufB);
}

template <int BEG, int END>
__device__ __forceinline__ __half2 tree2(const __half2* v) {
    if constexpr (END - BEG == 1) {
        return v[BEG];
    } else {
        constexpr int MID = (BEG + END) / 2;
        return __hadd2(tree2<BEG, MID>(v), tree2<MID, END>(v));
    }
}

__device__ __forceinline__ void w_to_f4(uint2 wb, float2& lo, float2& hi) {
    lo = __half22float2(*reinterpret_cast<__half2*>(&wb.x));
    hi = __half22float2(*reinterpret_cast<__half2*>(&wb.y));
}

template <int C0>
__device__ __forceinline__ void gather_core(
    const uint2* __restrict__ fb, const int* __restrict__ orow,
    const uint2* __restrict__ wres2, int lane,
    float4& acc0, float4& acc1)
{
#pragma unroll
    for (int l = 0; l < PATH_LEN; l++) {
        int4 o0 = *(const int4*)(orow + l * N_PATHS);
        int4 o1 = *(const int4*)(orow + l * N_PATHS + 4);
        uint2 r[8];
        r[0] = __ldg(fb + o0.x); r[1] = __ldg(fb + o0.y);
        r[2] = __ldg(fb + o0.z); r[3] = __ldg(fb + o0.w);
        r[4] = __ldg(fb + o1.x); r[5] = __ldg(fb + o1.y);
        r[6] = __ldg(fb + o1.z); r[7] = __ldg(fb + o1.w);

        __half2 va[8], vb[8];
#pragma unroll
        for (int i = 0; i < 8; i++) {
            va[i] = *reinterpret_cast<__half2*>(&r[i].x);
            vb[i] = *reinterpret_cast<__half2*>(&r[i].y);
        }

        uint2 wb0 = __ldg(wres2 + (size_t)l * (HID / 4) + lane);
        uint2 wb1 = __ldg(wres2 + (size_t)(PATH_LEN + l) * (HID / 4) + lane);

        if constexpr (C0 > 0) {
            __half2 sa = tree2<0, C0>(va);
            __half2 sb = tree2<0, C0>(vb);
            float2 fa = __half22float2(sa);
            float2 fbv = __half22float2(sb);
            float2 wlo, whi; w_to_f4(wb0, wlo, whi);
            acc0.x = fmaf(fa.x,  wlo.x, acc0.x);
            acc0.y = fmaf(fa.y,  wlo.y, acc0.y);
            acc0.z = fmaf(fbv.x, whi.x, acc0.z);
            acc0.w = fmaf(fbv.y, whi.y, acc0.w);
        }
        if constexpr (C0 < N_PATHS) {
            __half2 sa = tree2<C0, N_PATHS>(va);
            __half2 sb = tree2<C0, N_PATHS>(vb);
            float2 fa = __half22float2(sa);
            float2 fbv = __half22float2(sb);
            float2 wlo, whi; w_to_f4(wb1, wlo, whi);
            acc1.x = fmaf(fa.x,  wlo.x, acc1.x);
            acc1.y = fmaf(fa.y,  wlo.y, acc1.y);
            acc1.z = fmaf(fbv.x, whi.x, acc1.z);
            acc1.w = fmaf(fbv.y, whi.y, acc1.w);
        }
    }
}

__global__ void __launch_bounds__(256, 4)
gather_kernel(const int* __restrict__ paths, const int* __restrict__ ptypes,
              int feats_sel, int layer)
{
    const uint2* __restrict__ feats2 = (const uint2*)buf_ptr(feats_sel);
    const uint2* __restrict__ wres2 =
        (const uint2*)(g_wres_h + (size_t)layer * N_TYPES * PATH_LEN * HID);

    __shared__ int off_s[8][N_PATHS * PATH_LEN];   // [slot][l*8 + pos]
    __shared__ int types_s[N_PATHS];

    const int tid  = threadIdx.x;
    const int slot = tid >> 5;
    const int lane = tid & 31;
    const int n    = blockIdx.x * 8 + slot;

    if (tid < N_PATHS) types_s[tid] = ptypes[tid];
    __syncthreads();

    unsigned tmask = 0;
#pragma unroll
    for (int p = 0; p < N_PATHS; p++)
        tmask |= (types_s[p] ? 1u : 0u) << p;
    const int c0 = N_PATHS - __popc(tmask);

    {
        int i  = tid * 2;
        int sl = i >> 6;
        int r  = i & 63;
        int p  = r >> 3, l = r & 7;
        int nn = blockIdx.x * 8 + sl;
        int2 v = *(const int2*)(paths + (size_t)p * (N_NODES * PATH_LEN)
                                + (size_t)nn * PATH_LEN + l);
        unsigned below = (1u << p) - 1u;
        int pos = (tmask >> p) & 1
                ? c0 + __popc(tmask & below)
                : __popc(~tmask & below & 0xFFu);
        off_s[sl][l * N_PATHS + pos]       = v.x * (HID / 4);
        off_s[sl][(l + 1) * N_PATHS + pos] = v.y * (HID / 4);
    }
    __syncthreads();

    const uint2* fb = feats2 + lane;
    const int* orow = off_s[slot];

    float4 acc0 = make_float4(0.f, 0.f, 0.f, 0.f);
    float4 acc1 = make_float4(0.f, 0.f, 0.f, 0.f);

    switch (c0) {
        case 0: gather_core<0>(fb, orow, wres2, lane, acc0, acc1); break;
        case 1: gather_core<1>(fb, orow, wres2, lane, acc0, acc1); break;
        case 2: gather_core<2>(fb, orow, wres2, lane, acc0, acc1); break;
        case 3: gather_core<3>(fb, orow, wres2, lane, acc0, acc1); break;
        case 4: gather_core<4>(fb, orow, wres2, lane, acc0, acc1); break;
        case 5: gather_core<5>(fb, orow, wres2, lane, acc0, acc1); break;
        case 6: gather_core<6>(fb, orow, wres2, lane, acc0, acc1); break;
        case 7: gather_core<7>(fb, orow, wres2, lane, acc0, acc1); break;
        default: gather_core<8>(fb, orow, wres2, lane, acc0, acc1); break;
    }

    // store fout as fp16: node row = 256 halves = 64 uint2
    uint2* fo = (uint2*)(g_fout + (size_t)n * (N_TYPES * HID));
    __half2 a01 = __floats2half2_rn(acc0.x, acc0.y);
    __half2 a23 = __floats2half2_rn(acc0.z, acc0.w);
    __half2 b01 = __floats2half2_rn(acc1.x, acc1.y);
    __half2 b23 = __floats2half2_rn(acc1.z, acc1.w);
    fo[lane]      = make_uint2(*(uint32_t*)&a01, *(uint32_t*)&a23);
    fo[32 + lane] = make_uint2(*(uint32_t*)&b01, *(uint32_t*)&b23);
}

// ============================================================================
extern "C" void kernel_launch(void* const* d_in, const int* in_sizes, int n_in,
                              void* d_out, int out_size)
{
    const float* input_x    = (const float*)d_in[0];
    const int*   paths      = (const int*)d_in[1];
    const int*   ptypes     = (const int*)d_in[2];
    const float* fc_in_w    = (const float*)d_in[3];
    const float* fc_in_b    = (const float*)d_in[4];
    const float* fc_out_w   = (const float*)d_in[5];
    const float* fc_out_b   = (const float*)d_in[6];
    const float* layer_fc_w = (const float*)d_in[7];
    const float* path_w     = (const float*)d_in[8];
    float* out = (float*)d_out;

    constexpr int LDSH = 40, NST = 4;
    constexpr size_t SM_128 = (size_t)NST * (64 * LDSH + 128 * LDSH) * 2; // 61440
    constexpr size_t SM_64  = (size_t)NST * (64 * LDSH + 64 * LDSH) * 2;  // 40960

    // idempotent; safe to call every launch (not a stream operation)
    cudaFuncSetAttribute(gemm_h_kernel<IN_DIM, HID, 0, true>,
                         cudaFuncAttributeMaxDynamicSharedMemorySize, SM_128);
    cudaFuncSetAttribute(gemm_h_kernel<N_TYPES * HID, HID, 1, true>,
                         cudaFuncAttributeMaxDynamicSharedMemorySize, SM_128);
    cudaFuncSetAttribute(gemm_h_kernel<HID, OUT_DIM, 0, false>,
                         cudaFuncAttributeMaxDynamicSharedMemorySize, SM_64);

    __half *in_feats_p, *bufA_p, *bufB_p, *fout_p, *x_h_p;
    __half *w_in_p, *w_layer_p, *w_out_p;
    cudaGetSymbolAddress((void**)&in_feats_p, g_in_feats);
    cudaGetSymbolAddress((void**)&bufA_p, g_bufA);
    cudaGetSymbolAddress((void**)&bufB_p, g_bufB);
    cudaGetSymbolAddress((void**)&fout_p, g_fout);
    cudaGetSymbolAddress((void**)&x_h_p, g_x_h);
    cudaGetSymbolAddress((void**)&w_in_p, g_w_in);
    cudaGetSymbolAddress((void**)&w_layer_p, g_w_layer);
    cudaGetSymbolAddress((void**)&w_out_p, g_w_out);

    const dim3 blk(256);
    const dim3 ggrd((N_NODES + 63) / 64);

    prep_kernel<<<(N_NODES * IN_DIM + 255) / 256, blk>>>(
        input_x, fc_in_w, layer_fc_w, fc_out_w, path_w, ptypes);

    gemm_h_kernel<IN_DIM, HID, 0, true><<<ggrd, blk, SM_128>>>(
        x_h_p, w_in_p, fc_in_b, nullptr, nullptr, in_feats_p);

    int cur = 0;  // feats = g_in_feats
    __half* bufs[3] = {in_feats_p, bufA_p, bufB_p};
    for (int i = 0; i < N_LAYERS; i++) {
        gather_kernel<<<N_NODES / 8, blk>>>(paths, ptypes, cur, i);
        int nxt = (cur == 1) ? 2 : 1;
        gemm_h_kernel<N_TYPES * HID, HID, 1, true><<<ggrd, blk, SM_128>>>(
            fout_p, w_layer_p + (size_t)i * HID * (N_TYPES * HID), nullptr,
            bufs[cur], in_feats_p, bufs[nxt]);
        cur = nxt;
    }

    gemm_h_kernel<HID, OUT_DIM, 0, false><<<ggrd, blk, SM_64>>>(
        bufs[cur], w_out_p, fc_out_b, nullptr, nullptr, out);
}

// round 17
// speedup vs baseline: 1.0503x; 1.0503x over previous
#include <cuda_runtime.h>
#include <cuda_fp16.h>
#include <cstdint>

#define N_NODES 20000
#define IN_DIM 256
#define HID 128
#define OUT_DIM 64
#define N_LAYERS 4
#define N_PATHS 8
#define PATH_LEN 8
#define N_TYPES 2

// -------- scratch (no allocations allowed; device globals) --------
__device__ __align__(16) __half g_in_feats[N_NODES * HID];
__device__ __align__(16) __half g_bufA[N_NODES * HID];
__device__ __align__(16) __half g_bufB[N_NODES * HID];
__device__ __align__(16) __half g_fout[N_NODES * N_TYPES * HID];
__device__ __align__(16) __half g_x_h[N_NODES * IN_DIM];
__device__ __align__(16) __half g_wres_h[N_LAYERS * N_TYPES * PATH_LEN * HID];

#define W_IN_ELEMS    (HID * IN_DIM)
#define W_LAYER_ELEMS (N_LAYERS * HID * N_TYPES * HID)
#define W_OUT_ELEMS   (OUT_DIM * HID)
__device__ __align__(16) __half g_w_in[W_IN_ELEMS];
__device__ __align__(16) __half g_w_layer[W_LAYER_ELEMS];
__device__ __align__(16) __half g_w_out[W_OUT_ELEMS];

__device__ __forceinline__ void mma_f16(
    float& d0, float& d1, float& d2, float& d3,
    uint32_t a0, uint32_t a1, uint32_t a2, uint32_t a3,
    uint32_t b0, uint32_t b1)
{
    asm volatile(
        "mma.sync.aligned.m16n8k16.row.col.f32.f16.f16.f32 "
        "{%0,%1,%2,%3}, {%4,%5,%6,%7}, {%8,%9}, {%0,%1,%2,%3};\n"
        : "+f"(d0), "+f"(d1), "+f"(d2), "+f"(d3)
        : "r"(a0), "r"(a1), "r"(a2), "r"(a3), "r"(b0), "r"(b1));
}

__device__ __forceinline__ void cp_async16(void* smem_dst, const void* gsrc,
                                           int src_bytes) {
    uint32_t s = (uint32_t)__cvta_generic_to_shared(smem_dst);
    asm volatile("cp.async.cg.shared.global [%0], [%1], 16, %2;\n"
                 :: "r"(s), "l"(gsrc), "r"(src_bytes));
}
__device__ __forceinline__ void cp_async_commit() {
    asm volatile("cp.async.commit_group;\n");
}
template <int N>
__device__ __forceinline__ void cp_async_wait() {
    asm volatile("cp.async.wait_group %0;\n" :: "n"(N));
}

// ============================================================================
// Fused prep: fp16 conversions of x / weights, and wres = pw/count as fp16.
// ============================================================================
__global__ void prep_kernel(const float* __restrict__ x,
                            const float* __restrict__ w_in,
                            const float* __restrict__ w_layer,
                            const float* __restrict__ w_out,
                            const float* __restrict__ pw,
                            const int* __restrict__ ptypes)
{
    int i = blockIdx.x * blockDim.x + threadIdx.x;
    if (i < N_NODES * IN_DIM) g_x_h[i] = __float2half(__ldg(x + i));
    if (i < W_IN_ELEMS)       g_w_in[i] = __float2half(__ldg(w_in + i));
    if (i < W_LAYER_ELEMS)    g_w_layer[i] = __float2half(__ldg(w_layer + i));
    if (i < W_OUT_ELEMS)      g_w_out[i] = __float2half(__ldg(w_out + i));
    if (i < N_LAYERS * N_TYPES * PATH_LEN * HID) {
        int t = (i / (PATH_LEN * HID)) % N_TYPES;
        int cnt = 0;
#pragma unroll
        for (int p = 0; p < N_PATHS; p++) cnt += (__ldg(ptypes + p) == t);
        float inv = cnt > 0 ? 1.0f / (float)cnt : 0.0f;
        g_wres_h[i] = __float2half(__ldg(pw + i) * inv);
    }
}

// ============================================================================
// FP16 tensor-core GEMM (m16n8k16, fp32 accum), 3-stage cp.async pipeline,
// ONE barrier per k-tile with CORRECT ordering:
//   wait(stage kt done) -> __syncthreads (all warps done reading the buffer
//   that will be overwritten) -> issue(kt+NST-1) -> commit -> MMA(stage kt)
//   C[M, BN] = EPI( A[M, KDIM] @ W[BN, KDIM]^T )
//   EPI==0: relu(acc + bias[n]);  EPI==1: 0.8*relu(acc)+0.1*pre+0.1*inf
//   OUTH: store C (and read pre/inf) as __half; else fp32.
// Block tile 64 x BN, 256 threads: 2 warps M x 4 warps N.
// ============================================================================
template <int KDIM, int BN, int EPI, bool OUTH>
__global__ void __launch_bounds__(256, 3)
gemm_h_kernel(const __half* __restrict__ A, const __half* __restrict__ W,
              const float* __restrict__ bias, const void* __restrict__ pre,
              const void* __restrict__ inf, void* __restrict__ C)
{
    constexpr int BM = 64, BK = 32, LDSH = 40, NST = 3;
    constexpr int NTW = BN / 32;
    constexpr int ASZ = BM * LDSH;
    constexpr int BSZ = BN * LDSH;
    constexpr int KTILES = KDIM / BK;
    constexpr int NCA = (BM * BK) / 8 / 256;
    constexpr int NCB = (BN * BK) / 8 / 256;

    extern __shared__ __half smh[];
    __half* As = smh;
    __half* Bs = smh + NST * ASZ;

    const int tid    = threadIdx.x;
    const int lane   = tid & 31;
    const int warp   = tid >> 5;
    const int warp_m = warp & 1;
    const int warp_n = warp >> 1;
    const int gid    = lane >> 2;
    const int tig    = lane & 3;
    const int m0     = blockIdx.x * BM;

    float acc[2][NTW][4];
#pragma unroll
    for (int mt = 0; mt < 2; mt++)
#pragma unroll
        for (int nt = 0; nt < NTW; nt++)
#pragma unroll
            for (int r = 0; r < 4; r++) acc[mt][nt][r] = 0.f;

    auto issue = [&](int kt, int b) {
#pragma unroll
        for (int i = 0; i < NCA; i++) {
            int c    = tid + i * 256;
            int row  = c >> 2, colh = (c & 3) << 3;
            int ok   = (m0 + row) < N_NODES ? 16 : 0;
            cp_async16(As + b * ASZ + row * LDSH + colh,
                       A + (size_t)(m0 + row) * KDIM + kt * BK + colh, ok);
        }
#pragma unroll
        for (int i = 0; i < NCB; i++) {
            int c    = tid + i * 256;
            int row  = c >> 2, colh = (c & 3) << 3;
            cp_async16(Bs + b * BSZ + row * LDSH + colh,
                       W + (size_t)row * KDIM + kt * BK + colh, 16);
        }
    };

    // prologue: stages 0..NST-2 (NST-1 committed groups)
#pragma unroll
    for (int s = 0; s < NST - 1; s++) {
        if (s < KTILES) issue(s, s);
        cp_async_commit();
    }

    for (int kt = 0; kt < KTILES; kt++) {
        // stage kt complete (committed groups: NST-1+kt; keep NST-2 pending)
        cp_async_wait<NST - 2>();
        __syncthreads();   // all warps finished reading buffer (kt-1)%NST

        // now safe to overwrite buffer (kt+NST-1)%NST == (kt-1)%NST
        if (kt + NST - 1 < KTILES) issue(kt + NST - 1, (kt + NST - 1) % NST);
        cp_async_commit();

        const __half* Ab = As + (kt % NST) * ASZ;
        const __half* Bb = Bs + (kt % NST) * BSZ;
#pragma unroll
        for (int kk = 0; kk < BK / 16; kk++) {
            const int kb = kk * 16;
            uint32_t a[2][4];
#pragma unroll
            for (int mt = 0; mt < 2; mt++) {
                int r = warp_m * 32 + mt * 16 + gid;
                a[mt][0] = *(const uint32_t*)(Ab + r * LDSH + kb + 2 * tig);
                a[mt][1] = *(const uint32_t*)(Ab + (r + 8) * LDSH + kb + 2 * tig);
                a[mt][2] = *(const uint32_t*)(Ab + r * LDSH + kb + 8 + 2 * tig);
                a[mt][3] = *(const uint32_t*)(Ab + (r + 8) * LDSH + kb + 8 + 2 * tig);
            }
            uint32_t b[NTW][2];
#pragma unroll
            for (int nt = 0; nt < NTW; nt++) {
                int c = warp_n * (NTW * 8) + nt * 8 + gid;
                b[nt][0] = *(const uint32_t*)(Bb + c * LDSH + kb + 2 * tig);
                b[nt][1] = *(const uint32_t*)(Bb + c * LDSH + kb + 8 + 2 * tig);
            }
#pragma unroll
            for (int mt = 0; mt < 2; mt++)
#pragma unroll
                for (int nt = 0; nt < NTW; nt++)
                    mma_f16(acc[mt][nt][0], acc[mt][nt][1],
                            acc[mt][nt][2], acc[mt][nt][3],
                            a[mt][0], a[mt][1], a[mt][2], a[mt][3],
                            b[nt][0], b[nt][1]);
        }
    }

#pragma unroll
    for (int mt = 0; mt < 2; mt++) {
#pragma unroll
        for (int half = 0; half < 2; half++) {
            int row = m0 + warp_m * 32 + mt * 16 + half * 8 + gid;
            if (row >= N_NODES) continue;
#pragma unroll
            for (int nt = 0; nt < NTW; nt++) {
                int col = warp_n * (NTW * 8) + nt * 8 + 2 * tig;
                float v0 = acc[mt][nt][half * 2 + 0];
                float v1 = acc[mt][nt][half * 2 + 1];
                size_t off = (size_t)row * BN + col;
                if constexpr (EPI == 0) {
                    v0 = fmaxf(v0 + bias[col], 0.f);
                    v1 = fmaxf(v1 + bias[col + 1], 0.f);
                } else {
                    float2 p2, f2;
                    if constexpr (OUTH) {
                        p2 = __half22float2(*(const __half2*)((const __half*)pre + off));
                        f2 = __half22float2(*(const __half2*)((const __half*)inf + off));
                    } else {
                        p2 = *(const float2*)((const float*)pre + off);
                        f2 = *(const float2*)((const float*)inf + off);
                    }
                    v0 = 0.8f * fmaxf(v0, 0.f) + 0.1f * p2.x + 0.1f * f2.x;
                    v1 = 0.8f * fmaxf(v1, 0.f) + 0.1f * p2.y + 0.1f * f2.y;
                }
                if constexpr (OUTH) {
                    *(__half2*)((__half*)C + off) = __floats2half2_rn(v0, v1);
                } else {
                    *(float2*)((float*)C + off) = make_float2(v0, v1);
                }
            }
        }
    }
}

// ============================================================================
// Gather: 1 warp per node, lane covers 4 channels, l-outer, type-permuted
// indices, half2 pairwise-tree path sum, fp16 weights. tmask from __ldg.
// 8 nodes per 256-thread block.
// ============================================================================
__device__ __forceinline__ __half* buf_ptr(int s) {
    return s == 0 ? g_in_feats : (s == 1 ? g_bufA : g_bufB);
}

template <int BEG, int END>
__device__ __forceinline__ __half2 tree2(const __half2* v) {
    if constexpr (END - BEG == 1) {
        return v[BEG];
    } else {
        constexpr int MID = (BEG + END) / 2;
        return __hadd2(tree2<BEG, MID>(v), tree2<MID, END>(v));
    }
}

__device__ __forceinline__ void w_to_f4(uint2 wb, float2& lo, float2& hi) {
    lo = __half22float2(*reinterpret_cast<__half2*>(&wb.x));
    hi = __half22float2(*reinterpret_cast<__half2*>(&wb.y));
}

template <int C0>
__device__ __forceinline__ void gather_core(
    const uint2* __restrict__ fb, const int* __restrict__ orow,
    const uint2* __restrict__ wres2, int lane,
    float4& acc0, float4& acc1)
{
#pragma unroll
    for (int l = 0; l < PATH_LEN; l++) {
        int4 o0 = *(const int4*)(orow + l * N_PATHS);
        int4 o1 = *(const int4*)(orow + l * N_PATHS + 4);
        uint2 r[8];
        r[0] = __ldg(fb + o0.x); r[1] = __ldg(fb + o0.y);
        r[2] = __ldg(fb + o0.z); r[3] = __ldg(fb + o0.w);
        r[4] = __ldg(fb + o1.x); r[5] = __ldg(fb + o1.y);
        r[6] = __ldg(fb + o1.z); r[7] = __ldg(fb + o1.w);

        __half2 va[8], vb[8];
#pragma unroll
        for (int i = 0; i < 8; i++) {
            va[i] = *reinterpret_cast<__half2*>(&r[i].x);
            vb[i] = *reinterpret_cast<__half2*>(&r[i].y);
        }

        uint2 wb0 = __ldg(wres2 + (size_t)l * (HID / 4) + lane);
        uint2 wb1 = __ldg(wres2 + (size_t)(PATH_LEN + l) * (HID / 4) + lane);

        if constexpr (C0 > 0) {
            __half2 sa = tree2<0, C0>(va);
            __half2 sb = tree2<0, C0>(vb);
            float2 fa = __half22float2(sa);
            float2 fbv = __half22float2(sb);
            float2 wlo, whi; w_to_f4(wb0, wlo, whi);
            acc0.x = fmaf(fa.x,  wlo.x, acc0.x);
            acc0.y = fmaf(fa.y,  wlo.y, acc0.y);
            acc0.z = fmaf(fbv.x, whi.x, acc0.z);
            acc0.w = fmaf(fbv.y, whi.y, acc0.w);
        }
        if constexpr (C0 < N_PATHS) {
            __half2 sa = tree2<C0, N_PATHS>(va);
            __half2 sb = tree2<C0, N_PATHS>(vb);
            float2 fa = __half22float2(sa);
            float2 fbv = __half22float2(sb);
            float2 wlo, whi; w_to_f4(wb1, wlo, whi);
            acc1.x = fmaf(fa.x,  wlo.x, acc1.x);
            acc1.y = fmaf(fa.y,  wlo.y, acc1.y);
            acc1.z = fmaf(fbv.x, whi.x, acc1.z);
            acc1.w = fmaf(fbv.y, whi.y, acc1.w);
        }
    }
}

__global__ void __launch_bounds__(256, 4)
gather_kernel(const int* __restrict__ paths, const int* __restrict__ ptypes,
              int feats_sel, int layer)
{
    const uint2* __restrict__ feats2 = (const uint2*)buf_ptr(feats_sel);
    const uint2* __restrict__ wres2 =
        (const uint2*)(g_wres_h + (size_t)layer * N_TYPES * PATH_LEN * HID);

    __shared__ int off_s[8][N_PATHS * PATH_LEN];   // [slot][l*8 + pos]

    const int tid  = threadIdx.x;
    const int slot = tid >> 5;
    const int lane = tid & 31;
    const int n    = blockIdx.x * 8 + slot;

    unsigned tmask = 0;
#pragma unroll
    for (int p = 0; p < N_PATHS; p++)
        tmask |= (__ldg(ptypes + p) ? 1u : 0u) << p;
    const int c0 = N_PATHS - __popc(tmask);

    {
        int i  = tid * 2;
        int sl = i >> 6;
        int r  = i & 63;
        int p  = r >> 3, l = r & 7;
        int nn = blockIdx.x * 8 + sl;
        int2 v = *(const int2*)(paths + (size_t)p * (N_NODES * PATH_LEN)
                                + (size_t)nn * PATH_LEN + l);
        unsigned below = (1u << p) - 1u;
        int pos = (tmask >> p) & 1
                ? c0 + __popc(tmask & below)
                : __popc(~tmask & below & 0xFFu);
        off_s[sl][l * N_PATHS + pos]       = v.x * (HID / 4);
        off_s[sl][(l + 1) * N_PATHS + pos] = v.y * (HID / 4);
    }
    __syncthreads();

    const uint2* fb = feats2 + lane;
    const int* orow = off_s[slot];

    float4 acc0 = make_float4(0.f, 0.f, 0.f, 0.f);
    float4 acc1 = make_float4(0.f, 0.f, 0.f, 0.f);

    switch (c0) {
        case 0: gather_core<0>(fb, orow, wres2, lane, acc0, acc1); break;
        case 1: gather_core<1>(fb, orow, wres2, lane, acc0, acc1); break;
        case 2: gather_core<2>(fb, orow, wres2, lane, acc0, acc1); break;
        case 3: gather_core<3>(fb, orow, wres2, lane, acc0, acc1); break;
        case 4: gather_core<4>(fb, orow, wres2, lane, acc0, acc1); break;
        case 5: gather_core<5>(fb, orow, wres2, lane, acc0, acc1); break;
        case 6: gather_core<6>(fb, orow, wres2, lane, acc0, acc1); break;
        case 7: gather_core<7>(fb, orow, wres2, lane, acc0, acc1); break;
        default: gather_core<8>(fb, orow, wres2, lane, acc0, acc1); break;
    }

    // store fout as fp16: node row = 256 halves = 64 uint2
    uint2* fo = (uint2*)(g_fout + (size_t)n * (N_TYPES * HID));
    __half2 a01 = __floats2half2_rn(acc0.x, acc0.y);
    __half2 a23 = __floats2half2_rn(acc0.z, acc0.w);
    __half2 b01 = __floats2half2_rn(acc1.x, acc1.y);
    __half2 b23 = __floats2half2_rn(acc1.z, acc1.w);
    fo[lane]      = make_uint2(*(uint32_t*)&a01, *(uint32_t*)&a23);
    fo[32 + lane] = make_uint2(*(uint32_t*)&b01, *(uint32_t*)&b23);
}

// ============================================================================
extern "C" void kernel_launch(void* const* d_in, const int* in_sizes, int n_in,
                              void* d_out, int out_size)
{
    const float* input_x    = (const float*)d_in[0];
    const int*   paths      = (const int*)d_in[1];
    const int*   ptypes     = (const int*)d_in[2];
    const float* fc_in_w    = (const float*)d_in[3];
    const float* fc_in_b    = (const float*)d_in[4];
    const float* fc_out_w   = (const float*)d_in[5];
    const float* fc_out_b   = (const float*)d_in[6];
    const float* layer_fc_w = (const float*)d_in[7];
    const float* path_w     = (const float*)d_in[8];
    float* out = (float*)d_out;

    constexpr int LDSH = 40, NST = 3;
    constexpr size_t SM_128 = (size_t)NST * (64 * LDSH + 128 * LDSH) * 2; // 46080
    constexpr size_t SM_64  = (size_t)NST * (64 * LDSH + 64 * LDSH) * 2;  // 30720

    __half *in_feats_p, *bufA_p, *bufB_p, *fout_p, *x_h_p;
    __half *w_in_p, *w_layer_p, *w_out_p;
    cudaGetSymbolAddress((void**)&in_feats_p, g_in_feats);
    cudaGetSymbolAddress((void**)&bufA_p, g_bufA);
    cudaGetSymbolAddress((void**)&bufB_p, g_bufB);
    cudaGetSymbolAddress((void**)&fout_p, g_fout);
    cudaGetSymbolAddress((void**)&x_h_p, g_x_h);
    cudaGetSymbolAddress((void**)&w_in_p, g_w_in);
    cudaGetSymbolAddress((void**)&w_layer_p, g_w_layer);
    cudaGetSymbolAddress((void**)&w_out_p, g_w_out);

    const dim3 blk(256);
    const dim3 ggrd((N_NODES + 63) / 64);

    prep_kernel<<<(N_NODES * IN_DIM + 255) / 256, blk>>>(
        input_x, fc_in_w, layer_fc_w, fc_out_w, path_w, ptypes);

    gemm_h_kernel<IN_DIM, HID, 0, true><<<ggrd, blk, SM_128>>>(
        x_h_p, w_in_p, fc_in_b, nullptr, nullptr, in_feats_p);

    int cur = 0;  // feats = g_in_feats
    __half* bufs[3] = {in_feats_p, bufA_p, bufB_p};
    for (int i = 0; i < N_LAYERS; i++) {
        gather_kernel<<<N_NODES / 8, blk>>>(paths, ptypes, cur, i);
        int nxt = (cur == 1) ? 2 : 1;
        gemm_h_kernel<N_TYPES * HID, HID, 1, true><<<ggrd, blk, SM_128>>>(
            fout_p, w_layer_p + (size_t)i * HID * (N_TYPES * HID), nullptr,
            bufs[cur], in_feats_p, bufs[nxt]);
        cur = nxt;
    }

    gemm_h_kernel<HID, OUT_DIM, 0, false><<<ggrd, blk, SM_64>>>(
        bufs[cur], w_out_p, fc_out_b, nullptr, nullptr, out);
}